// round 16
// baseline (speedup 1.0000x reference)
#include <cuda_runtime.h>

#define B      2048
#define NHID   1024
#define NC     224
#define TPC    225
#define KP     256              // padded bottom-partial row stride (floats)
#define SPLIT  8                // bottom d-splits (128 d each)
#define TS     4                // top d-splits (256 d each)
#define EC     8                // examples per chunk
#define DC     128
#define XS8    12               // padded x-tile stride (floats), 48B (16B-aligned)
#define NTOPB  (TS * (B / EC))  // 1024 top blocks
#define NBOT   (NC * SPLIT)     // 1792 bottom blocks
#define MAXN   96

// Scratch (device globals — no allocation allowed)
__device__ float g_part [(size_t)SPLIT * B * KP];   // bottom partials
__device__ float g_tpart[(size_t)TS * B * NC];      // top partials

// ---------------------------------------------------------------------------
// Inner 128-d GEMM chunk. Thread t handles k = t + 64q (q=0..3), 8 examples.
// Weights double-buffered 2 d-steps ahead. kv[q]: per-q load validity.
// acc layout: acc[q*8 + e].
// ---------------------------------------------------------------------------
__device__ __forceinline__ void gemm128(const float* __restrict__ Wp, // W + d0*ws + t
                                        int ws, const bool kv[4],
                                        const float* __restrict__ sx,
                                        float* __restrict__ acc) {
    float w0[4], w1[4], n0[4], n1[4];
#pragma unroll
    for (int q = 0; q < 4; q++) {
        n0[q] = kv[q] ? Wp[0 * ws + 64 * q] : 0.0f;
        n1[q] = kv[q] ? Wp[1 * ws + 64 * q] : 0.0f;
    }
    for (int dd = 0; dd < DC; dd += 2) {
#pragma unroll
        for (int q = 0; q < 4; q++) { w0[q] = n0[q]; w1[q] = n1[q]; }
        if (dd + 2 < DC) {
            const float* p0 = Wp + (dd + 2) * ws;
            const float* p1 = Wp + (dd + 3) * ws;
#pragma unroll
            for (int q = 0; q < 4; q++) {
                n0[q] = kv[q] ? p0[64 * q] : 0.0f;
                n1[q] = kv[q] ? p1[64 * q] : 0.0f;
            }
        }
#pragma unroll
        for (int h = 0; h < 2; h++) {
            const float4* xp = (const float4*)&sx[(dd + h) * XS8];
            float4 xa = xp[0], xb = xp[1];
            const float* w = h ? w1 : w0;
#pragma unroll
            for (int q = 0; q < 4; q++) {
                acc[q * 8 + 0] += xa.x * w[q];
                acc[q * 8 + 1] += xa.y * w[q];
                acc[q * 8 + 2] += xa.z * w[q];
                acc[q * 8 + 3] += xa.w * w[q];
                acc[q * 8 + 4] += xb.x * w[q];
                acc[q * 8 + 5] += xb.y * w[q];
                acc[q * 8 + 6] += xb.z * w[q];
                acc[q * 8 + 7] += xb.w * w[q];
            }
        }
    }
}

// x-tile loader: 8 examples x 128 d, transposed [dd][e], stride XS8.
__device__ __forceinline__ void load_xtile(const float* __restrict__ X,
                                           const int* __restrict__ bi,
                                           int d0, int tid,
                                           float* __restrict__ sx) {
    int e   = tid & 7;
    int seg = tid >> 3;                       // 0..7, 16 d each
    const float4* xr = (const float4*)(X + (size_t)bi[e] * NHID + d0 + seg * 16);
#pragma unroll
    for (int j = 0; j < 4; j++) {
        float4 v = xr[j];
        int dd = seg * 16 + j * 4;
        sx[(dd + 0) * XS8 + e] = v.x;
        sx[(dd + 1) * XS8 + e] = v.y;
        sx[(dd + 2) * XS8 + e] = v.z;
        sx[(dd + 3) * XS8 + e] = v.w;
    }
}

// ---------------------------------------------------------------------------
// Main fused kernel, 64-thread blocks.
//   blocks [0, NTOPB):             top (d-split, 8-example chunk) -> g_tpart
//   blocks [NTOPB, NTOPB + NBOT):  bottom (class, d-split)        -> g_part
// ---------------------------------------------------------------------------
__global__ __launch_bounds__(64, 12) void k_main(const float* __restrict__ X,
                                                 const float* __restrict__ Wt,
                                                 const int*   __restrict__ labels,
                                                 const float* __restrict__ Wb) {
    __shared__ __align__(16) float s_x[DC * XS8];
    const int tid = threadIdx.x;

    if (blockIdx.x < NTOPB) {
        // ---------------- TOP ----------------
        const int chunk = blockIdx.x & 255;    // 256 e-chunks
        const int ts    = blockIdx.x >> 8;     // 0..3
        const int b0    = chunk * EC;
        const int dbase = ts * (NHID / TS);    // 256-d span

        __shared__ int s_bi[EC];
        if (tid < EC) s_bi[tid] = b0 + tid;
        __syncthreads();

        float acc[32];
#pragma unroll
        for (int i = 0; i < 32; i++) acc[i] = 0.0f;

        bool kv[4];
#pragma unroll
        for (int q = 0; q < 4; q++) kv[q] = (tid + 64 * q) < NC;

        for (int d0 = dbase; d0 < dbase + NHID / TS; d0 += DC) {
            __syncthreads();
            load_xtile(X, s_bi, d0, tid, s_x);
            __syncthreads();
            gemm128(Wt + (size_t)d0 * NC + tid, NC, kv, s_x, acc);
        }

        float* dst = g_tpart + (size_t)ts * B * NC;
#pragma unroll
        for (int q = 0; q < 4; q++) {
            int k = tid + 64 * q;
            if (k < NC) {
#pragma unroll
                for (int e = 0; e < EC; e++)
                    dst[(size_t)(b0 + e) * NC + k] = acc[q * 8 + e];
            }
        }
    } else {
        // ---------------- BOTTOM ----------------
        const int bid = blockIdx.x - NTOPB;
        const int c   = bid % NC;
        const int sp  = bid / NC;
        const int d0  = sp * (NHID / SPLIT);   // 128-d span == DC

        __shared__ int s_idx[MAXN];
        __shared__ int s_n;
        __shared__ int s_bi[EC];

        if (tid == 0) s_n = 0;
        __syncthreads();
#pragma unroll 4
        for (int b = tid; b < B; b += 64) {
            if (labels[b] / TPC == c) {
                int p = atomicAdd(&s_n, 1);
                if (p < MAXN) s_idx[p] = b;
            }
        }
        __syncthreads();
        int n = s_n < MAXN ? s_n : MAXN;
        if (n == 0) return;

        const float* Wc = Wb + (size_t)c * NHID * TPC;
        bool kv[4];
#pragma unroll
        for (int q = 0; q < 4; q++) kv[q] = (tid + 64 * q) < TPC;

        float* dst = g_part + (size_t)sp * B * KP;

        for (int e0 = 0; e0 < n; e0 += EC) {
            int rem = n - e0;
            if (rem > EC) rem = EC;
            __syncthreads();
            if (tid < EC) {
                int ee = (tid < rem) ? tid : (rem - 1);
                s_bi[tid] = s_idx[e0 + ee];
            }
            __syncthreads();
            load_xtile(X, s_bi, d0, tid, s_x);
            __syncthreads();

            float acc[32];
#pragma unroll
            for (int i = 0; i < 32; i++) acc[i] = 0.0f;

            gemm128(Wc + (size_t)d0 * TPC + tid, TPC, kv, s_x, acc);

            // store: k = tid + 64q < KP=256 always in-bounds; garbage cols
            // >= 225 are masked in k_final.
#pragma unroll
            for (int e = 0; e < EC; e++) {
                if (e < rem) {
                    float* row = dst + (size_t)s_bi[e] * KP + tid;
#pragma unroll
                    for (int q = 0; q < 4; q++) row[64 * q] = acc[q * 8 + e];
                }
            }
        }
    }
}

// ---------------------------------------------------------------------------
// Final merge: sum partials + bias for both levels, two softmaxes, multiply.
// 1 warp per example; 512 blocks x 128 threads.
// ---------------------------------------------------------------------------
__global__ __launch_bounds__(128) void k_final(const int*   __restrict__ labels,
                                               const float* __restrict__ bt,
                                               const float* __restrict__ bb,
                                               float* __restrict__ out) {
    const int warp = threadIdx.x >> 5, lane = threadIdx.x & 31;
    const int b    = blockIdx.x * 4 + warp;
    const int lab  = labels[b];
    const int c    = lab / TPC;
    const int word = lab - c * TPC;

    // ---- top: 224 cols ----
    float vt[7];
#pragma unroll
    for (int q = 0; q < 7; q++) {
        int kk = lane + q * 32;
        float s = bt[kk];
#pragma unroll
        for (int ts = 0; ts < TS; ts++)
            s += g_tpart[((size_t)ts * B + b) * NC + kk];
        vt[q] = s;
    }
    float mt = -1e30f;
#pragma unroll
    for (int q = 0; q < 7; q++) mt = fmaxf(mt, vt[q]);
#pragma unroll
    for (int o = 16; o; o >>= 1) mt = fmaxf(mt, __shfl_xor_sync(0xffffffffu, mt, o));
    float st = 0.0f, tt = 0.0f;
#pragma unroll
    for (int q = 0; q < 7; q++) {
        int kk = lane + q * 32;
        float e = expf(vt[q] - mt);
        st += e;
        if (kk == c) tt = e;
    }
#pragma unroll
    for (int o = 16; o; o >>= 1) {
        st += __shfl_xor_sync(0xffffffffu, st, o);
        tt += __shfl_xor_sync(0xffffffffu, tt, o);
    }

    // ---- bottom: 225 cols padded to 256, float4 reads ----
    float4 a0 = make_float4(0.f, 0.f, 0.f, 0.f);
    float4 a1 = make_float4(0.f, 0.f, 0.f, 0.f);
#pragma unroll
    for (int sp = 0; sp < SPLIT; sp++) {
        const float4* p = (const float4*)(g_part + ((size_t)sp * B + b) * KP);
        float4 t0 = p[lane];
        float4 t1 = p[lane + 32];
        a0.x += t0.x; a0.y += t0.y; a0.z += t0.z; a0.w += t0.w;
        a1.x += t1.x; a1.y += t1.y; a1.z += t1.z; a1.w += t1.w;
    }
    float v[8] = {a0.x, a0.y, a0.z, a0.w, a1.x, a1.y, a1.z, a1.w};
    int col[8];
#pragma unroll
    for (int q = 0; q < 4; q++) { col[q] = 4 * lane + q; col[4 + q] = 128 + 4 * lane + q; }
#pragma unroll
    for (int q = 0; q < 8; q++) {
        if (col[q] < TPC) v[q] += bb[c * TPC + col[q]];
        else              v[q] = -1e30f;
    }
    float m = -1e30f;
#pragma unroll
    for (int q = 0; q < 8; q++) m = fmaxf(m, v[q]);
#pragma unroll
    for (int o = 16; o; o >>= 1) m = fmaxf(m, __shfl_xor_sync(0xffffffffu, m, o));
    float s = 0.0f, t = 0.0f;
#pragma unroll
    for (int q = 0; q < 8; q++) {
        if (col[q] < TPC) {
            float e = expf(v[q] - m);
            s += e;
            if (col[q] == word) t = e;
        }
    }
#pragma unroll
    for (int o = 16; o; o >>= 1) {
        s += __shfl_xor_sync(0xffffffffu, s, o);
        t += __shfl_xor_sync(0xffffffffu, t, o);
    }
    if (lane == 0) out[b] = (tt / st) * (t / s);
}

// Launch-parity shim so ncu's skip lands on k_main.
__global__ void k_nop() {}

// ---------------------------------------------------------------------------
extern "C" void kernel_launch(void* const* d_in, const int* in_sizes, int n_in,
                              void* d_out, int out_size) {
    const float* inputs   = (const float*)d_in[0];
    const int*   labels   = (const int*)d_in[1];
    const float* W_top    = (const float*)d_in[2];
    const float* b_top    = (const float*)d_in[3];
    const float* W_bottom = (const float*)d_in[4];
    const float* b_bottom = (const float*)d_in[5];
    float* out = (float*)d_out;

    k_main <<<NTOPB + NBOT, 64>>>(inputs, W_top, labels, W_bottom);
    k_final<<<B / 4, 128>>>(labels, b_top, b_bottom, out);
    k_nop  <<<1, 32>>>();
}

// round 17
// speedup vs baseline: 1.3490x; 1.3490x over previous
#include <cuda_runtime.h>

#define B      2048
#define NHID   1024
#define NC     224
#define TPC    225
#define KP     256              // padded bottom-partial row stride (floats)
#define TBE    16
#define SPLIT  8                // bottom d-splits
#define DSPAN  (NHID / SPLIT)   // 128
#define TS     4                // top d-splits
#define TSPAN  (NHID / TS)      // 256
#define DC     128
#define XS     20               // padded x-tile stride (floats)
#define NBOT   (NC * SPLIT)     // 1792 bottom blocks
#define NTOPB  (TS * (B / TBE)) // 512 top blocks
#define MAXN   96

// Scratch (device globals — no allocation allowed)
__device__ float g_part [(size_t)SPLIT * B * KP];   // 16.8 MB bottom partials
__device__ float g_tpart[(size_t)TS * B * NC];      // 7.34 MB top partials

// ---------------------------------------------------------------------------
// Inner GEMM chunk: acc[EL] += x[EL][128] * w[128]; x from smem (broadcast),
// w via strided LDG, software-pipelined ONE dd4-group ahead so the 4-LDG
// batch issues ~64 FFMAs before first consumption.
// ---------------------------------------------------------------------------
template <int EL>
__device__ __forceinline__ void fma_block(const float* __restrict__ wk, int wstride,
                                          const float* __restrict__ sx, float* acc) {
    float w[4], nw[4];
#pragma unroll
    for (int j = 0; j < 4; j++) nw[j] = wk[j * wstride];
#pragma unroll 2
    for (int dd4 = 0; dd4 < DC; dd4 += 4) {
#pragma unroll
        for (int j = 0; j < 4; j++) w[j] = nw[j];
        if (dd4 + 4 < DC) {
            const float* p = wk + (dd4 + 4) * wstride;
#pragma unroll
            for (int j = 0; j < 4; j++) nw[j] = p[j * wstride];
        }
#pragma unroll
        for (int j = 0; j < 4; j++) {
            const float4* xp = (const float4*)&sx[(dd4 + j) * XS];
#pragma unroll
            for (int q = 0; q < EL / 4; q++) {
                float4 x = xp[q];
                acc[4 * q + 0] += x.x * w[j];
                acc[4 * q + 1] += x.y * w[j];
                acc[4 * q + 2] += x.z * w[j];
                acc[4 * q + 3] += x.w * w[j];
            }
        }
    }
}

// ---------------------------------------------------------------------------
// Main fused kernel.
//   blocks [0, NBOT):          bottom per-(class, d-split) GEMM -> g_part
//   blocks [NBOT, NBOT+NTOPB): top per-(d-split, example-tile) GEMM -> g_tpart
// ---------------------------------------------------------------------------
__global__ __launch_bounds__(256, 3) void k_main(const float* __restrict__ X,
                                                 const float* __restrict__ Wt,
                                                 const int*   __restrict__ labels,
                                                 const float* __restrict__ Wb) {
    __shared__ float s_x[DC * XS];
    const int tid = threadIdx.x;

    if (blockIdx.x < NBOT) {
        // ---------------- BOTTOM ----------------
        const int c  = blockIdx.x % NC;
        const int sp = blockIdx.x / NC;
        const int d0 = sp * DSPAN;            // DSPAN == DC

        __shared__ int s_idx[MAXN];
        __shared__ int s_n;
        __shared__ int s_bi[TBE];

        if (tid == 0) s_n = 0;
        __syncthreads();
        for (int b = tid; b < B; b += 256) {
            if (labels[b] / TPC == c) {
                int p = atomicAdd(&s_n, 1);
                if (p < MAXN) s_idx[p] = b;
            }
        }
        __syncthreads();
        int n = s_n < MAXN ? s_n : MAXN;
        if (n == 0) return;

        const float* Wc = Wb + (size_t)c * NHID * TPC;
        const int k = tid;                    // word col, active when < 225

        for (int e0 = 0; e0 < n; e0 += TBE) {
            int rem = n - e0;
            if (rem > TBE) rem = TBE;
            const int ne = (rem > 8) ? 16 : 8;
            __syncthreads();
            if (tid < TBE) {
                int ee = (tid < rem) ? tid : (rem - 1);
                s_bi[tid] = s_idx[e0 + ee];
            }
            __syncthreads();
            for (int i = tid; i < ne * DC; i += 256) {
                int e  = i >> 7;
                int dd = i & 127;
                s_x[dd * XS + e] = X[(size_t)s_bi[e] * NHID + d0 + dd];
            }
            __syncthreads();

            float acc[TBE];
#pragma unroll
            for (int e = 0; e < TBE; e++) acc[e] = 0.0f;

            if (k < TPC) {
                const float* wk = Wc + (size_t)d0 * TPC + k;
                if (ne == 16) fma_block<16>(wk, TPC, s_x, acc);
                else          fma_block<8>(wk, TPC, s_x, acc);

                float* dst = g_part + (size_t)sp * B * KP;
#pragma unroll
                for (int e = 0; e < TBE; e++)
                    if (e < rem) dst[(size_t)s_bi[e] * KP + k] = acc[e];
            }
        }
    } else {
        // ---------------- TOP (d-split) ----------------
        const int tb = blockIdx.x - NBOT;     // 0..511
        const int ts = tb >> 7;               // d-split 0..3
        const int b0 = (tb & 127) * TBE;
        const int dbase = ts * TSPAN;
        const int k = tid;                    // class col, active when < 224

        float acc[TBE];
#pragma unroll
        for (int e = 0; e < TBE; e++) acc[e] = 0.0f;

        for (int d0 = dbase; d0 < dbase + TSPAN; d0 += DC) {
            __syncthreads();
            for (int i = tid; i < TBE * DC; i += 256) {
                int e  = i >> 7;
                int dd = i & 127;
                s_x[dd * XS + e] = X[(b0 + e) * NHID + d0 + dd];
            }
            __syncthreads();
            if (k < NC) {
                const float* wk = Wt + (size_t)d0 * NC + k;
                fma_block<16>(wk, NC, s_x, acc);
            }
        }

        if (k < NC) {
            float* dst = g_tpart + (size_t)ts * B * NC;
#pragma unroll
            for (int e = 0; e < TBE; e++)
                dst[(size_t)(b0 + e) * NC + k] = acc[e];
        }
    }
}

// ---------------------------------------------------------------------------
// Final merge: sum partials + bias for both levels, two softmaxes, multiply.
// 1 warp per example; 512 blocks x 128 threads.
// ---------------------------------------------------------------------------
__global__ __launch_bounds__(128) void k_final(const int*   __restrict__ labels,
                                               const float* __restrict__ bt,
                                               const float* __restrict__ bb,
                                               float* __restrict__ out) {
    const int warp = threadIdx.x >> 5, lane = threadIdx.x & 31;
    const int b    = blockIdx.x * 4 + warp;
    const int lab  = labels[b];
    const int c    = lab / TPC;
    const int word = lab - c * TPC;

    // ---- top: 224 cols, lane holds cols lane+32q, q=0..6 ----
    float vt[7];
#pragma unroll
    for (int q = 0; q < 7; q++) {
        int kk = lane + q * 32;
        float s = bt[kk];
#pragma unroll
        for (int ts = 0; ts < TS; ts++)
            s += g_tpart[((size_t)ts * B + b) * NC + kk];
        vt[q] = s;
    }
    float mt = -1e30f;
#pragma unroll
    for (int q = 0; q < 7; q++) mt = fmaxf(mt, vt[q]);
#pragma unroll
    for (int o = 16; o; o >>= 1) mt = fmaxf(mt, __shfl_xor_sync(0xffffffffu, mt, o));
    float st = 0.0f, tt = 0.0f;
#pragma unroll
    for (int q = 0; q < 7; q++) {
        int kk = lane + q * 32;
        float e = expf(vt[q] - mt);
        st += e;
        if (kk == c) tt = e;
    }
#pragma unroll
    for (int o = 16; o; o >>= 1) {
        st += __shfl_xor_sync(0xffffffffu, st, o);
        tt += __shfl_xor_sync(0xffffffffu, tt, o);
    }

    // ---- bottom: 225 cols padded to 256, float4 reads ----
    float4 a0 = make_float4(0.f, 0.f, 0.f, 0.f);
    float4 a1 = make_float4(0.f, 0.f, 0.f, 0.f);
#pragma unroll
    for (int sp = 0; sp < SPLIT; sp++) {
        const float4* p = (const float4*)(g_part + ((size_t)sp * B + b) * KP);
        float4 t0 = p[lane];
        float4 t1 = p[lane + 32];
        a0.x += t0.x; a0.y += t0.y; a0.z += t0.z; a0.w += t0.w;
        a1.x += t1.x; a1.y += t1.y; a1.z += t1.z; a1.w += t1.w;
    }
    float v[8] = {a0.x, a0.y, a0.z, a0.w, a1.x, a1.y, a1.z, a1.w};
    int col[8];
#pragma unroll
    for (int q = 0; q < 4; q++) { col[q] = 4 * lane + q; col[4 + q] = 128 + 4 * lane + q; }
#pragma unroll
    for (int q = 0; q < 8; q++) {
        if (col[q] < TPC) v[q] += bb[c * TPC + col[q]];
        else              v[q] = -1e30f;
    }
    float m = -1e30f;
#pragma unroll
    for (int q = 0; q < 8; q++) m = fmaxf(m, v[q]);
#pragma unroll
    for (int o = 16; o; o >>= 1) m = fmaxf(m, __shfl_xor_sync(0xffffffffu, m, o));
    float s = 0.0f, t = 0.0f;
#pragma unroll
    for (int q = 0; q < 8; q++) {
        if (col[q] < TPC) {
            float e = expf(v[q] - m);
            s += e;
            if (col[q] == word) t = e;
        }
    }
#pragma unroll
    for (int o = 16; o; o >>= 1) {
        s += __shfl_xor_sync(0xffffffffu, s, o);
        t += __shfl_xor_sync(0xffffffffu, t, o);
    }
    if (lane == 0) out[b] = (tt / st) * (t / s);
}

// Launch-parity shim so ncu's skip lands on k_main.
__global__ void k_nop() {}

// ---------------------------------------------------------------------------
extern "C" void kernel_launch(void* const* d_in, const int* in_sizes, int n_in,
                              void* d_out, int out_size) {
    const float* inputs   = (const float*)d_in[0];
    const int*   labels   = (const int*)d_in[1];
    const float* W_top    = (const float*)d_in[2];
    const float* b_top    = (const float*)d_in[3];
    const float* W_bottom = (const float*)d_in[4];
    const float* b_bottom = (const float*)d_in[5];
    float* out = (float*)d_out;

    k_main <<<NBOT + NTOPB, 256>>>(inputs, W_top, labels, W_bottom);
    k_final<<<B / 4, 128>>>(labels, b_top, b_bottom, out);
    k_nop  <<<1, 32>>>();
}